// round 14
// baseline (speedup 1.0000x reference)
#include <cuda_runtime.h>

// GARCH(1,1): h[t] = (omega + alpha*r[t-1]^2) + beta*h[t-1], h[0] = var(r, ddof=1)
// out[0..n) = sqrt(h), out[n..2n) = h
//
// R13 structure (padded-smem staging, in-place per-thread recurrence,
// ping-pong Hillis-Steele exact stitch, carry at read, float4 STG, f32x2
// variance, fused last-block ticket fixup) with ALL shared-memory traffic
// vectorized to 128-bit: the r[t-1] shift is absorbed in registers via
// shfl_down (lane 31 loads its neighbor float4 directly), so driver quads
// land k-aligned and phases 1/2/4 use STS.128/LDS.128 exclusively.
// Padding at float4 granularity: slot(q) = q + q/8 (conflict-free for both
// consecutive-q and 9*tid+j access patterns).
// beta<1 => contractive (beta^128 ~ 1e-9 << 1e-3 tol): 128-elem warm-up halo;
// intra-block stitch exact. True h[t] = h_hat[t] + beta^t*h0 (linearity),
// patched by the last block, which also reduces the fp32 variance partials.

#define TPB   256
#define CPT   32
#define TILE  (TPB*CPT)        // 8192
#define NF4   (TILE/4)         // 2048 float4s
#define HALO  128
#define OPB   (TILE - HALO)    // 8064 outputs per block (div by 4)
#define QOUT  (OPB/4)          // 2016
#define FIXN  256
#define MAXB  4096

__device__ double   g_psum[MAXB];
__device__ double   g_psumsq[MAXB];
__device__ unsigned g_ticket = 0;

__device__ __forceinline__ int pad4(int q) { return q + (q >> 3); }        // float4 slots
__device__ __forceinline__ int sidx(int e) { return e + ((e >> 5) << 2); } // scalar view

__device__ __forceinline__ float fsqrt_ap(float x) {
    float y; asm("sqrt.approx.f32 %0, %1;" : "=f"(y) : "f"(x)); return y;
}
// packed f32x2 (sm_100+)
__device__ __forceinline__ unsigned long long pk2(float lo, float hi) {
    unsigned long long d;
    asm("mov.b64 %0, {%1, %2};" : "=l"(d) : "r"(__float_as_uint(lo)), "r"(__float_as_uint(hi)));
    return d;
}
__device__ __forceinline__ void upk2(unsigned long long v, float& lo, float& hi) {
    unsigned a, b; asm("mov.b64 {%0, %1}, %2;" : "=r"(a), "=r"(b) : "l"(v));
    lo = __uint_as_float(a); hi = __uint_as_float(b);
}
__device__ __forceinline__ unsigned long long mul2(unsigned long long a, unsigned long long b) {
    unsigned long long d; asm("mul.rn.f32x2 %0, %1, %2;" : "=l"(d) : "l"(a), "l"(b)); return d;
}
__device__ __forceinline__ unsigned long long add2(unsigned long long a, unsigned long long b) {
    unsigned long long d; asm("add.rn.f32x2 %0, %1, %2;" : "=l"(d) : "l"(a), "l"(b)); return d;
}

__global__ void __launch_bounds__(TPB)
garch_fused(const float* __restrict__ r,
            const float* __restrict__ omega_p,
            const float* __restrict__ alpha_p,
            const float* __restrict__ beta_p,
            float* __restrict__ out,
            int n, int nblocks, int write_h)
{
    __shared__ __align__(16) float4 dpad[NF4 + NF4/8];   // 2304 f4 = 36.9KB
    __shared__ float  s0[TPB], s1[TPB];                  // ping-pong scan
    __shared__ float  powtab[CPT];                       // beta^(j+1)
    __shared__ double wsum[TPB/32], wsq[TPB/32];
    __shared__ unsigned s_ticket;
    __shared__ float  sh0;

    const int   tid   = threadIdx.x;
    const int   b     = blockIdx.x;
    const int   lane  = tid & 31;
    const unsigned FULL = 0xFFFFFFFFu;
    const float omega = *omega_p;
    const float alpha = *alpha_p;
    const float beta  = *beta_p;

    // outputs: t in [b*OPB, b*OPB+OPB) ∩ [0,n). tile index k = t - t0.
    const long long t0 = (long long)b * OPB - HALO;   // k=0 <-> t=t0
    const long long A  = t0 - 1;                      // driver r index: g = A + k

    float vs = 0.0f, vq = 0.0f;
    unsigned long long vs2 = 0ull, vq2 = 0ull;

    const bool fast = (b >= 1) && ((long long)(b + 1) * OPB <= (long long)n)
                      && ((n & 3) == 0);

    // ---- Phase 1: driver quads d[k]=omega+alpha*r[A+k]^2, k-aligned STS.128 ----
    if (fast) {
        // L_q = r4[q] covers k = 4q-3 .. 4q  (A-3 is 16B aligned: A ≡ 3 mod 4)
        const float4* __restrict__ r4 = (const float4*)(r + (A - 3));
        #pragma unroll
        for (int it = 0; it < 8; ++it) {
            int q = tid + it * TPB;
            float4 L = r4[q];
            float Rx = __shfl_down_sync(FULL, L.x, 1);   // L_{q+1}.x for lane<31
            float Ry = __shfl_down_sync(FULL, L.y, 1);
            float Rz = __shfl_down_sync(FULL, L.z, 1);
            if (lane == 31) {                            // neighbor is next warp
                float4 Nb = r4[q + 1];                   // in-bounds (fast blocks)
                Rx = Nb.x; Ry = Nb.y; Rz = Nb.z;
                if (q == NF4 - 1) {                      // top: k=8189..8191
                    vs += (Rx + Ry) + Rz;
                    vq += (Rx * Rx + Ry * Ry) + Rz * Rz;
                }
            }
            // driver quad for k = 4q..4q+3
            float4 D;
            D.x = fmaf(alpha, L.w * L.w, omega);
            D.y = fmaf(alpha, Rx * Rx, omega);
            D.z = fmaf(alpha, Ry * Ry, omega);
            D.w = fmaf(alpha, Rz * Rz, omega);
            dpad[pad4(q)] = D;

            if (it == 0) {                               // k0=4q-3: gate per elem
                int k0 = 4 * q - 3;
                if (k0 + 0 >= HALO) { vs += L.x; vq = fmaf(L.x, L.x, vq); }
                if (k0 + 1 >= HALO) { vs += L.y; vq = fmaf(L.y, L.y, vq); }
                if (k0 + 2 >= HALO) { vs += L.z; vq = fmaf(L.z, L.z, vq); }
                if (k0 + 3 >= HALO) { vs += L.w; vq = fmaf(L.w, L.w, vq); }
            } else {                                     // all k > HALO: f32x2
                unsigned long long v01 = pk2(L.x, L.y), v23 = pk2(L.z, L.w);
                vs2 = add2(vs2, v01);          vs2 = add2(vs2, v23);
                vq2 = add2(vq2, mul2(v01, v01));
                vq2 = add2(vq2, mul2(v23, v23));
            }
        }
    } else {
        float* dscal = (float*)dpad;
        #pragma unroll 4
        for (int it = 0; it < TILE / TPB; ++it) {
            int k = tid + it * TPB;
            long long g = A + k;
            float bb = 0.0f;
            if (g >= 0 && g <= (long long)n - 2) {
                float rv = r[g];
                float rr = rv * rv;
                bb = fmaf(alpha, rr, omega);
                if (k >= HALO) { vs += rv; vq += rr; }
            }
            dscal[sidx(k)] = bb;
        }
    }
    if (b == 0 && tid == 0) {                     // r[n-1]: variance only
        float rv = r[n - 1];
        vs += rv; vq = fmaf(rv, rv, vq);
    }
    __syncthreads();

    // ---- Phase 2: per-thread 32-chain from zero state, in place (.128) ----
    {
        float h = 0.0f;
        #pragma unroll
        for (int j = 0; j < 8; ++j) {
            int slot = 9 * tid + j;                      // pad4(8*tid + j)
            float4 d = dpad[slot];
            h = fmaf(beta, h, d.x); d.x = h;
            h = fmaf(beta, h, d.y); d.y = h;
            h = fmaf(beta, h, d.z); d.z = h;
            h = fmaf(beta, h, d.w); d.w = h;
            dpad[slot] = d;
        }
        s0[tid] = h;
    }
    if (tid < CPT) {                              // powtab[j] = beta^(j+1)
        float p = 1.0f, bb = beta; int e = tid + 1;
        while (e) { if (e & 1) p *= bb; bb *= bb; e >>= 1; }
        powtab[tid] = p;
    }
    __syncthreads();

    // ---- Phase 3: exact stitch, ping-pong (1 barrier/step, 8 steps) ----
    {
        float bb2 = beta * beta, b4_ = bb2 * bb2, b8 = b4_ * b4_, b16 = b8 * b8;
        float m = b16 * b16;                      // beta^32
        #pragma unroll
        for (int step = 0; step < 8; ++step) {
            const float* src = (step & 1) ? s1 : s0;
            float*       dst = (step & 1) ? s0 : s1;
            int d = 1 << step;
            float v = src[tid];
            if (tid >= d) v = fmaf(m, src[tid - d], v);
            dst[tid] = v;
            m *= m;
            __syncthreads();
        }
    }

    // ---- Phase 4: carry at read (.128), vectorized stores ----
    if (fast) {
        // pj = 4*((tid)%8) is it-invariant: hoist the 4 powtab values
        const int pj = 4 * (tid & 7);
        const float pw0 = powtab[pj + 0], pw1 = powtab[pj + 1];
        const float pw2 = powtab[pj + 2], pw3 = powtab[pj + 3];
        #pragma unroll
        for (int it = 0; it < 8; ++it) {
            int q = tid + it * TPB;
            if (q < QOUT) {
                int qf = (HALO / 4) + q;                 // float4 index of k
                float4 hd = dpad[pad4(qf)];
                float cy = s0[(qf >> 3) + (HALO / 32) - 1];
                float h0 = fmaf(pw0, cy, hd.x);
                float h1 = fmaf(pw1, cy, hd.y);
                float h2 = fmaf(pw2, cy, hd.z);
                float h3 = fmaf(pw3, cy, hd.w);
                long long t = (long long)b * OPB + 4 * (long long)q;
                *(float4*)(out + t) = make_float4(fsqrt_ap(h0), fsqrt_ap(h1),
                                                  fsqrt_ap(h2), fsqrt_ap(h3));
                if (write_h) *(float4*)(out + n + t) = make_float4(h0, h1, h2, h3);
            }
        }
    } else {
        const float* dscal = (const float*)dpad;
        #pragma unroll 4
        for (int it = 0; it < TILE / TPB; ++it) {
            int k = tid + it * TPB;
            if (k < HALO) continue;
            long long t = t0 + k;
            if (t < (long long)n) {
                int c = k >> 5;
                float cy = (c > 0) ? s0[c - 1] : 0.0f;
                float h = fmaf(powtab[k & 31], cy, dscal[sidx(k)]);
                out[t] = fsqrt_ap(h);
                if (write_h) out[(long long)n + t] = h;
            }
        }
    }

    // ---- Phase 5: variance reduce -> per-block slot ----
    {
        float a_, b_;
        upk2(vs2, a_, b_); vs += a_ + b_;
        upk2(vq2, a_, b_); vq += a_ + b_;
    }
    #pragma unroll
    for (int off = 16; off; off >>= 1) {
        vs += __shfl_down_sync(FULL, vs, off);
        vq += __shfl_down_sync(FULL, vq, off);
    }
    const int wid = tid >> 5;
    if (lane == 0) { wsum[wid] = (double)vs; wsq[wid] = (double)vq; }
    __syncthreads();

    // ---- Phase 6: last-block ticket -> fused fixup ----
    if (tid == 0) {
        double a = 0.0, q = 0.0;
        #pragma unroll
        for (int w = 0; w < TPB / 32; ++w) { a += wsum[w]; q += wsq[w]; }
        g_psum[b]   = a;
        g_psumsq[b] = q;
        __threadfence();                          // cumulative release (post-bar)
        s_ticket = atomicAdd(&g_ticket, 1u);
    }
    __syncthreads();
    if (s_ticket != (unsigned)(nblocks - 1)) return;

    if (tid == 0) { g_ticket = 0; __threadfence(); }  // reset + acquire
    __syncthreads();

    double* red  = (double*)dpad;                 // reuse staging buffer
    double* red2 = red + TPB;
    {
        double a = 0.0, q = 0.0;
        for (int i = tid; i < nblocks; i += TPB) { a += g_psum[i]; q += g_psumsq[i]; }
        red[tid] = a; red2[tid] = q;
    }
    __syncthreads();
    for (int s = TPB / 2; s; s >>= 1) {
        if (tid < s) { red[tid] += red[tid + s]; red2[tid] += red2[tid + s]; }
        __syncthreads();
    }
    if (tid == 0) {
        double S = red[0], Q = red2[0];
        sh0 = (float)((Q - S * S / (double)n) / (double)(n - 1));
    }
    __syncthreads();

    const float h0v = sh0;
    const int   lim = (FIXN < n) ? FIXN : n;
    if (write_h) {
        // h[t] = h_hat[t] + beta^t * h0 (linearity); h_hat is in out[n+t]
        for (int t = tid; t < lim; t += TPB) {
            float bp = 1.0f, bb = beta; int e = t;
            while (e) { if (e & 1) bp *= bb; bb *= bb; e >>= 1; }
            float hh = (t == 0) ? h0v : fmaf(bp, h0v, out[(long long)n + t]);
            out[(long long)n + t] = hh;
            out[t] = fsqrt_ap(hh);
        }
    } else {
        if (tid == 0) {                           // rare fallback: serial prefix
            float h = h0v;
            out[0] = fsqrt_ap(h);
            for (int t = 1; t < lim; ++t) {
                float rv = r[t - 1];
                h = fmaf(beta, h, fmaf(alpha * rv, rv, omega));
                out[t] = fsqrt_ap(h);
            }
        }
    }
}

extern "C" void kernel_launch(void* const* d_in, const int* in_sizes, int n_in,
                              void* d_out, int out_size)
{
    const float* r  = (const float*)d_in[0];
    const float* om = (const float*)d_in[1];
    const float* al = (const float*)d_in[2];
    const float* be = (const float*)d_in[3];
    float* out = (float*)d_out;

    const int n = in_sizes[0];
    const int write_h = (out_size >= 2 * n) ? 1 : 0;

    int nblocks = (n + OPB - 1) / OPB;
    if (nblocks < 1)    nblocks = 1;
    if (nblocks > MAXB) nblocks = MAXB;

    garch_fused<<<nblocks, TPB>>>(r, om, al, be, out, n, nblocks, write_h);
}

// round 15
// speedup vs baseline: 1.0895x; 1.0895x over previous
#include <cuda_runtime.h>

// GARCH(1,1): h[t] = (omega + alpha*r[t-1]^2) + beta*h[t-1], h[0] = var(r, ddof=1)
// out[0..n) = sqrt(h), out[n..2n) = h
//
// This is the measured-best R3 fused kernel, byte-identical except for ONE
// change: the ticket release fence is executed by tid0 only (fence
// cumulativity after __syncthreads covers the whole block's prior stores),
// instead of 256 per-thread MEMBAR.GPUs draining in-flight STGs.
// beta<1 => contractive recurrence (beta^256 ~ 8e-19 < fp32 ulp): blocks
// compute the zero-state particular solution h_hat on tiles with a 256-elem
// warm-up halo; intra-block stitch is EXACT (Hillis-Steele with multipliers
// beta^(32*2^k)). True h[t] = h_hat[t] + beta^t*h0; the beta^t*h0 term only
// matters for t < ~100 and is patched by the LAST block to finish (ticket),
// which also reduces the fp32 variance partials.

#define TPB   256
#define CPT   32
#define TILE  (TPB*CPT)        // 8192
#define HALO  256
#define OPB   (TILE - HALO)    // 7936 outputs per block, 4-aligned
#define QOUT  (OPB/4)          // 1984
#define FIXN  256
#define MAXB  4096

__device__ double   g_psum[MAXB];
__device__ double   g_psumsq[MAXB];
__device__ unsigned g_ticket = 0;

__device__ __forceinline__ int padidx(int k) { return k + (k >> 5); }

__device__ __forceinline__ float fsqrt_ap(float x) {
    float y; asm("sqrt.approx.f32 %0, %1;" : "=f"(y) : "f"(x)); return y;
}
// packed f32x2 (sm_100+)
__device__ __forceinline__ unsigned long long pk2(float lo, float hi) {
    unsigned long long d;
    asm("mov.b64 %0, {%1, %2};" : "=l"(d) : "r"(__float_as_uint(lo)), "r"(__float_as_uint(hi)));
    return d;
}
__device__ __forceinline__ void upk2(unsigned long long v, float& lo, float& hi) {
    unsigned a, b; asm("mov.b64 {%0, %1}, %2;" : "=r"(a), "=r"(b) : "l"(v));
    lo = __uint_as_float(a); hi = __uint_as_float(b);
}
__device__ __forceinline__ unsigned long long mul2(unsigned long long a, unsigned long long b) {
    unsigned long long d; asm("mul.rn.f32x2 %0, %1, %2;" : "=l"(d) : "l"(a), "l"(b)); return d;
}
__device__ __forceinline__ unsigned long long add2(unsigned long long a, unsigned long long b) {
    unsigned long long d; asm("add.rn.f32x2 %0, %1, %2;" : "=l"(d) : "l"(a), "l"(b)); return d;
}
__device__ __forceinline__ unsigned long long fma2(unsigned long long a, unsigned long long b, unsigned long long c) {
    unsigned long long d; asm("fma.rn.f32x2 %0, %1, %2, %3;" : "=l"(d) : "l"(a), "l"(b), "l"(c)); return d;
}

__global__ void __launch_bounds__(TPB)
garch_fused(const float* __restrict__ r,
            const float* __restrict__ omega_p,
            const float* __restrict__ alpha_p,
            const float* __restrict__ beta_p,
            float* __restrict__ out,
            int n, int nblocks, int write_h)
{
    __shared__ __align__(16) float bpad[TILE + TILE/32];
    __shared__ float  sscan[TPB];
    __shared__ float  powtab[CPT];          // beta^(j+1)
    __shared__ double wsum[TPB/32], wsq[TPB/32];
    __shared__ unsigned s_ticket;
    __shared__ float  sh0;

    const int   tid   = threadIdx.x;
    const int   b     = blockIdx.x;
    const float omega = *omega_p;
    const float alpha = *alpha_p;
    const float beta  = *beta_p;

    // outputs: t in [b*OPB, b*OPB+OPB) ∩ [0,n). tile index k = t - t0.
    const long long t0 = (long long)b * OPB - HALO;   // k=0 <-> t=t0
    const long long A  = t0 - 1;                      // driver r index: g = A + k

    float vs = 0.0f, vq = 0.0f;
    unsigned long long vs2 = 0ull, vq2 = 0ull;

    const bool fast = (b >= 1) && ((long long)(b + 1) * OPB <= (long long)n)
                      && ((n & 3) == 0);

    // ---- Phase 1: drivers b[k] = omega + alpha*r[g]^2, variance partials ----
    if (fast) {
        const float4* __restrict__ r4 = (const float4*)(r + (A - 3)); // 16B aligned
        const unsigned long long alpha2 = pk2(alpha, alpha);
        const unsigned long long omega2 = pk2(omega, omega);
        #pragma unroll
        for (int it = 0; it < 8; ++it) {
            int q = tid + it * TPB;
            float4 v = r4[q];
            int k0 = 4 * q - 3;
            if (it == 0) {                       // edge: k may be <0 / <HALO
                #pragma unroll
                for (int e = 0; e < 4; ++e) {
                    int k = k0 + e;
                    float rv = (e == 0) ? v.x : (e == 1) ? v.y : (e == 2) ? v.z : v.w;
                    if (k >= 0) {
                        float rr = rv * rv;
                        bpad[padidx(k)] = fmaf(alpha, rr, omega);
                        if (k >= HALO) { vs += rv; vq += rr; }
                    }
                }
            } else {                              // packed f32x2 math
                unsigned long long v01 = pk2(v.x, v.y), v23 = pk2(v.z, v.w);
                unsigned long long rr01 = mul2(v01, v01), rr23 = mul2(v23, v23);
                unsigned long long b01 = fma2(alpha2, rr01, omega2);
                unsigned long long b23 = fma2(alpha2, rr23, omega2);
                vs2 = add2(vs2, v01);  vs2 = add2(vs2, v23);
                vq2 = add2(vq2, rr01); vq2 = add2(vq2, rr23);
                float x0, x1, x2, x3;
                upk2(b01, x0, x1); upk2(b23, x2, x3);
                bpad[padidx(k0 + 0)] = x0;
                bpad[padidx(k0 + 1)] = x1;
                bpad[padidx(k0 + 2)] = x2;
                bpad[padidx(k0 + 3)] = x3;
            }
        }
        if (tid < 3) {                            // top 3 elements k=8189..8191
            int k = TILE - 3 + tid;
            float rv = r[A + k];
            float rr = rv * rv;
            bpad[padidx(k)] = fmaf(alpha, rr, omega);
            vs += rv; vq += rr;
        }
    } else {
        #pragma unroll 4
        for (int it = 0; it < TILE / TPB; ++it) {
            int k = tid + it * TPB;
            long long g = A + k;
            float bb = 0.0f;
            if (g >= 0 && g <= (long long)n - 2) {
                float rv = r[g];
                float rr = rv * rv;
                bb = fmaf(alpha, rr, omega);
                if (k >= HALO) { vs += rv; vq += rr; }
            }
            bpad[padidx(k)] = bb;
        }
    }
    if (b == 0 && tid == 0) {                     // r[n-1]: variance only
        float rv = r[n - 1];
        vs += rv; vq = fmaf(rv, rv, vq);
    }
    __syncthreads();

    // ---- Phase 2: per-thread serial recurrence from zero state (in place) ----
    {
        float h = 0.0f;
        const int base = 33 * tid;                // padidx(tid*32)
        #pragma unroll
        for (int j = 0; j < CPT; ++j) {
            h = fmaf(beta, h, bpad[base + j]);
            bpad[base + j] = h;                   // p[j] stays in shared
        }
        sscan[tid] = h;
    }
    if (tid < CPT) {                              // powtab[j] = beta^(j+1)
        float p = 1.0f, bb = beta; int e = tid + 1;
        while (e) { if (e & 1) p *= bb; bb *= bb; e >>= 1; }
        powtab[tid] = p;
    }
    __syncthreads();

    // ---- Phase 3: exact stitch S_i = E_i + beta^32 * S_{i-1} ----
    float b2 = beta * beta, b4 = b2 * b2, b8 = b4 * b4, b16 = b8 * b8;
    float mpow = b16 * b16;                       // beta^32
    #pragma unroll
    for (int d = 1; d < TPB; d <<= 1) {
        float v  = sscan[tid];
        float lo = (tid >= d) ? sscan[tid - d] : 0.0f;
        __syncthreads();
        sscan[tid] = fmaf(mpow, lo, v);
        mpow *= mpow;
        __syncthreads();
    }

    // ---- Phase 4: apply carry at read, vectorized stores ----
    if (fast) {
        #pragma unroll
        for (int it = 0; it < 8; ++it) {
            int q = tid + it * TPB;
            if (q < QOUT) {
                int k  = HALO + 4 * q;
                int c  = k >> 5;                  // >= 8 here
                float cy = sscan[c - 1];
                int pb = padidx(k);               // 4 consecutive, no pad cross
                int pj = k & 31;
                float h0 = fmaf(powtab[pj + 0], cy, bpad[pb + 0]);
                float h1 = fmaf(powtab[pj + 1], cy, bpad[pb + 1]);
                float h2 = fmaf(powtab[pj + 2], cy, bpad[pb + 2]);
                float h3 = fmaf(powtab[pj + 3], cy, bpad[pb + 3]);
                long long t = (long long)b * OPB + 4 * (long long)q;
                float4 sv = make_float4(fsqrt_ap(h0), fsqrt_ap(h1),
                                        fsqrt_ap(h2), fsqrt_ap(h3));
                *(float4*)(out + t) = sv;
                if (write_h) *(float4*)(out + n + t) = make_float4(h0, h1, h2, h3);
            }
        }
    } else {
        #pragma unroll 4
        for (int it = 0; it < TILE / TPB; ++it) {
            int k = tid + it * TPB;
            if (k < HALO) continue;
            long long t = t0 + k;
            if (t < (long long)n) {
                int c = k >> 5;
                float cy = (c > 0) ? sscan[c - 1] : 0.0f;
                float h = fmaf(powtab[k & 31], cy, bpad[padidx(k)]);
                out[t] = fsqrt_ap(h);
                if (write_h) out[(long long)n + t] = h;
            }
        }
    }

    // ---- Phase 5: variance reduce -> per-block slot ----
    {
        float a_, b_;
        upk2(vs2, a_, b_); vs += a_ + b_;
        upk2(vq2, a_, b_); vq += a_ + b_;
    }
    unsigned msk = 0xFFFFFFFFu;
    #pragma unroll
    for (int off = 16; off; off >>= 1) {
        vs += __shfl_down_sync(msk, vs, off);
        vq += __shfl_down_sync(msk, vq, off);
    }
    const int wid = tid >> 5, lane = tid & 31;
    if (lane == 0) { wsum[wid] = (double)vs; wsq[wid] = (double)vq; }
    __syncthreads();
    if (tid == 0) {
        double a = 0.0, q = 0.0;
        #pragma unroll
        for (int w = 0; w < TPB / 32; ++w) { a += wsum[w]; q += wsq[w]; }
        g_psum[b]   = a;
        g_psumsq[b] = q;
    }

    // ---- Phase 6: last-block ticket -> fused fixup ----
    __syncthreads();
    // SINGLE release fence: after the barrier, tid0's fence orders every
    // thread's prior stores (fence cumulativity) before the ticket atomic.
    if (tid == 0) {
        __threadfence();
        s_ticket = atomicAdd(&g_ticket, 1u);
    }
    __syncthreads();
    if (s_ticket != (unsigned)(nblocks - 1)) return;

    if (tid == 0) { g_ticket = 0; __threadfence(); }  // reset + acquire
    __syncthreads();

    // deterministic reduction of per-block partials (bpad reused as scratch)
    double* red  = (double*)bpad;
    double* red2 = red + TPB;
    {
        double a = 0.0, q = 0.0;
        for (int i = tid; i < nblocks; i += TPB) { a += g_psum[i]; q += g_psumsq[i]; }
        red[tid] = a; red2[tid] = q;
    }
    __syncthreads();
    for (int s = TPB / 2; s; s >>= 1) {
        if (tid < s) { red[tid] += red[tid + s]; red2[tid] += red2[tid + s]; }
        __syncthreads();
    }
    if (tid == 0) {
        double S = red[0], Q = red2[0];
        sh0 = (float)((Q - S * S / (double)n) / (double)(n - 1));
    }
    __syncthreads();

    const float h0v = sh0;
    const int   lim = (FIXN < n) ? FIXN : n;
    if (write_h) {
        // h[t] = h_hat[t] + beta^t * h0 (linearity); h_hat is in out[n+t]
        for (int t = tid; t < lim; t += TPB) {
            float bp = 1.0f, bb = beta; int e = t;
            while (e) { if (e & 1) bp *= bb; bb *= bb; e >>= 1; }
            float hh = (t == 0) ? h0v : fmaf(bp, h0v, out[(long long)n + t]);
            out[(long long)n + t] = hh;
            out[t] = fsqrt_ap(hh);
        }
    } else {
        if (tid == 0) {                           // rare fallback: serial prefix
            float h = h0v;
            out[0] = fsqrt_ap(h);
            for (int t = 1; t < lim; ++t) {
                float rv = r[t - 1];
                h = fmaf(beta, h, fmaf(alpha * rv, rv, omega));
                out[t] = fsqrt_ap(h);
            }
        }
    }
}

extern "C" void kernel_launch(void* const* d_in, const int* in_sizes, int n_in,
                              void* d_out, int out_size)
{
    const float* r  = (const float*)d_in[0];
    const float* om = (const float*)d_in[1];
    const float* al = (const float*)d_in[2];
    const float* be = (const float*)d_in[3];
    float* out = (float*)d_out;

    const int n = in_sizes[0];
    const int write_h = (out_size >= 2 * n) ? 1 : 0;

    int nblocks = (n + OPB - 1) / OPB;
    if (nblocks < 1)    nblocks = 1;
    if (nblocks > MAXB) nblocks = MAXB;

    garch_fused<<<nblocks, TPB>>>(r, om, al, be, out, n, nblocks, write_h);
}

// round 16
// speedup vs baseline: 1.1151x; 1.0234x over previous
#include <cuda_runtime.h>

// GARCH(1,1): h[t] = (omega + alpha*r[t-1]^2) + beta*h[t-1], h[0] = var(r, ddof=1)
// out[0..n) = sqrt(h), out[n..2n) = h
//
// Split two-kernel design with PDL (programmatic dependent launch) to hide
// the fixup kernel's launch latency under the main kernel's execution:
//   - main: measured-best tile pipeline (padded-smem staging, f32x2 drivers,
//     in-place per-thread 32-chunk recurrence, exact Hillis-Steele stitch,
//     carry applied at read, float4 STG, sqrt.approx). Blocks retire clean
//     (no ticket/fence on the exit path). Each block fires
//     cudaTriggerProgrammaticLaunchCompletion() at start.
//   - fixup (1 block): launched with programmaticStreamSerializationAllowed;
//     calls cudaGridDependencySynchronize() before consuming main's outputs.
//     Reduces per-block variance partials -> h0, patches t<256 via linearity
//     h[t] = h_hat[t] + beta^t*h0. Host falls back to a normal launch if the
//     PDL attribute is rejected (grid-sync is then a no-op).
// beta<1 => contractive (beta^256 ~ 8e-19 < fp32 ulp): 256-elem warm-up halo
// per tile; intra-block stitch exact.

#define TPB   256
#define CPT   32
#define TILE  (TPB*CPT)        // 8192
#define HALO  256
#define OPB   (TILE - HALO)    // 7936 outputs per block, 4-aligned
#define QOUT  (OPB/4)          // 1984
#define FIXN  256
#define MAXB  4096

__device__ double g_psum[MAXB];
__device__ double g_psumsq[MAXB];

__device__ __forceinline__ int padidx(int k) { return k + (k >> 5); }

__device__ __forceinline__ float fsqrt_ap(float x) {
    float y; asm("sqrt.approx.f32 %0, %1;" : "=f"(y) : "f"(x)); return y;
}
// packed f32x2 (sm_100+)
__device__ __forceinline__ unsigned long long pk2(float lo, float hi) {
    unsigned long long d;
    asm("mov.b64 %0, {%1, %2};" : "=l"(d) : "r"(__float_as_uint(lo)), "r"(__float_as_uint(hi)));
    return d;
}
__device__ __forceinline__ void upk2(unsigned long long v, float& lo, float& hi) {
    unsigned a, b; asm("mov.b64 {%0, %1}, %2;" : "=r"(a), "=r"(b) : "l"(v));
    lo = __uint_as_float(a); hi = __uint_as_float(b);
}
__device__ __forceinline__ unsigned long long mul2(unsigned long long a, unsigned long long b) {
    unsigned long long d; asm("mul.rn.f32x2 %0, %1, %2;" : "=l"(d) : "l"(a), "l"(b)); return d;
}
__device__ __forceinline__ unsigned long long add2(unsigned long long a, unsigned long long b) {
    unsigned long long d; asm("add.rn.f32x2 %0, %1, %2;" : "=l"(d) : "l"(a), "l"(b)); return d;
}
__device__ __forceinline__ unsigned long long fma2(unsigned long long a, unsigned long long b, unsigned long long c) {
    unsigned long long d; asm("fma.rn.f32x2 %0, %1, %2, %3;" : "=l"(d) : "l"(a), "l"(b), "l"(c)); return d;
}

__global__ void __launch_bounds__(TPB)
garch_main(const float* __restrict__ r,
           const float* __restrict__ omega_p,
           const float* __restrict__ alpha_p,
           const float* __restrict__ beta_p,
           float* __restrict__ out,
           int n, int write_h)
{
#if __CUDA_ARCH__ >= 900
    if (threadIdx.x == 0) cudaTriggerProgrammaticLaunchCompletion();
#endif
    __shared__ __align__(16) float bpad[TILE + TILE/32];
    __shared__ float  sscan[TPB];
    __shared__ float  powtab[CPT];          // beta^(j+1)
    __shared__ double wsum[TPB/32], wsq[TPB/32];

    const int   tid   = threadIdx.x;
    const int   b     = blockIdx.x;
    const float omega = *omega_p;
    const float alpha = *alpha_p;
    const float beta  = *beta_p;

    // outputs: t in [b*OPB, b*OPB+OPB) ∩ [0,n). tile index k = t - t0.
    const long long t0 = (long long)b * OPB - HALO;   // k=0 <-> t=t0
    const long long A  = t0 - 1;                      // driver r index: g = A + k

    float vs = 0.0f, vq = 0.0f;
    unsigned long long vs2 = 0ull, vq2 = 0ull;

    const bool fast = (b >= 1) && ((long long)(b + 1) * OPB <= (long long)n)
                      && ((n & 3) == 0);

    // ---- Phase 1: drivers b[k] = omega + alpha*r[g]^2, variance partials ----
    if (fast) {
        const float4* __restrict__ r4 = (const float4*)(r + (A - 3)); // 16B aligned
        const unsigned long long alpha2 = pk2(alpha, alpha);
        const unsigned long long omega2 = pk2(omega, omega);
        #pragma unroll
        for (int it = 0; it < 8; ++it) {
            int q = tid + it * TPB;
            float4 v = r4[q];
            int k0 = 4 * q - 3;
            if (it == 0) {                       // edge: k may be <0 / <HALO
                #pragma unroll
                for (int e = 0; e < 4; ++e) {
                    int k = k0 + e;
                    float rv = (e == 0) ? v.x : (e == 1) ? v.y : (e == 2) ? v.z : v.w;
                    if (k >= 0) {
                        float rr = rv * rv;
                        bpad[padidx(k)] = fmaf(alpha, rr, omega);
                        if (k >= HALO) { vs += rv; vq += rr; }
                    }
                }
            } else {                              // packed f32x2 math
                unsigned long long v01 = pk2(v.x, v.y), v23 = pk2(v.z, v.w);
                unsigned long long rr01 = mul2(v01, v01), rr23 = mul2(v23, v23);
                unsigned long long b01 = fma2(alpha2, rr01, omega2);
                unsigned long long b23 = fma2(alpha2, rr23, omega2);
                vs2 = add2(vs2, v01);  vs2 = add2(vs2, v23);
                vq2 = add2(vq2, rr01); vq2 = add2(vq2, rr23);
                float x0, x1, x2, x3;
                upk2(b01, x0, x1); upk2(b23, x2, x3);
                bpad[padidx(k0 + 0)] = x0;
                bpad[padidx(k0 + 1)] = x1;
                bpad[padidx(k0 + 2)] = x2;
                bpad[padidx(k0 + 3)] = x3;
            }
        }
        if (tid < 3) {                            // top 3 elements k=8189..8191
            int k = TILE - 3 + tid;
            float rv = r[A + k];
            float rr = rv * rv;
            bpad[padidx(k)] = fmaf(alpha, rr, omega);
            vs += rv; vq += rr;
        }
    } else {
        #pragma unroll 4
        for (int it = 0; it < TILE / TPB; ++it) {
            int k = tid + it * TPB;
            long long g = A + k;
            float bb = 0.0f;
            if (g >= 0 && g <= (long long)n - 2) {
                float rv = r[g];
                float rr = rv * rv;
                bb = fmaf(alpha, rr, omega);
                if (k >= HALO) { vs += rv; vq += rr; }
            }
            bpad[padidx(k)] = bb;
        }
    }
    if (b == 0 && tid == 0) {                     // r[n-1]: variance only
        float rv = r[n - 1];
        vs += rv; vq = fmaf(rv, rv, vq);
    }
    __syncthreads();

    // ---- Phase 2: per-thread serial recurrence from zero state (in place) ----
    {
        float h = 0.0f;
        const int base = 33 * tid;                // padidx(tid*32)
        #pragma unroll
        for (int j = 0; j < CPT; ++j) {
            h = fmaf(beta, h, bpad[base + j]);
            bpad[base + j] = h;                   // p[j] stays in shared
        }
        sscan[tid] = h;
    }
    if (tid < CPT) {                              // powtab[j] = beta^(j+1)
        float p = 1.0f, bb = beta; int e = tid + 1;
        while (e) { if (e & 1) p *= bb; bb *= bb; e >>= 1; }
        powtab[tid] = p;
    }
    __syncthreads();

    // ---- Phase 3: exact stitch S_i = E_i + beta^32 * S_{i-1} ----
    float b2 = beta * beta, b4 = b2 * b2, b8 = b4 * b4, b16 = b8 * b8;
    float mpow = b16 * b16;                       // beta^32
    #pragma unroll
    for (int d = 1; d < TPB; d <<= 1) {
        float v  = sscan[tid];
        float lo = (tid >= d) ? sscan[tid - d] : 0.0f;
        __syncthreads();
        sscan[tid] = fmaf(mpow, lo, v);
        mpow *= mpow;
        __syncthreads();
    }

    // ---- Phase 4: apply carry at read, vectorized stores ----
    if (fast) {
        #pragma unroll
        for (int it = 0; it < 8; ++it) {
            int q = tid + it * TPB;
            if (q < QOUT) {
                int k  = HALO + 4 * q;
                int c  = k >> 5;                  // >= 8 here
                float cy = sscan[c - 1];
                int pb = padidx(k);               // 4 consecutive, no pad cross
                int pj = k & 31;
                float h0 = fmaf(powtab[pj + 0], cy, bpad[pb + 0]);
                float h1 = fmaf(powtab[pj + 1], cy, bpad[pb + 1]);
                float h2 = fmaf(powtab[pj + 2], cy, bpad[pb + 2]);
                float h3 = fmaf(powtab[pj + 3], cy, bpad[pb + 3]);
                long long t = (long long)b * OPB + 4 * (long long)q;
                float4 sv = make_float4(fsqrt_ap(h0), fsqrt_ap(h1),
                                        fsqrt_ap(h2), fsqrt_ap(h3));
                *(float4*)(out + t) = sv;
                if (write_h) *(float4*)(out + n + t) = make_float4(h0, h1, h2, h3);
            }
        }
    } else {
        #pragma unroll 4
        for (int it = 0; it < TILE / TPB; ++it) {
            int k = tid + it * TPB;
            if (k < HALO) continue;
            long long t = t0 + k;
            if (t < (long long)n) {
                int c = k >> 5;
                float cy = (c > 0) ? sscan[c - 1] : 0.0f;
                float h = fmaf(powtab[k & 31], cy, bpad[padidx(k)]);
                out[t] = fsqrt_ap(h);
                if (write_h) out[(long long)n + t] = h;
            }
        }
    }

    // ---- Phase 5: variance reduce -> per-block slot ----
    {
        float a_, b_;
        upk2(vs2, a_, b_); vs += a_ + b_;
        upk2(vq2, a_, b_); vq += a_ + b_;
    }
    unsigned msk = 0xFFFFFFFFu;
    #pragma unroll
    for (int off = 16; off; off >>= 1) {
        vs += __shfl_down_sync(msk, vs, off);
        vq += __shfl_down_sync(msk, vq, off);
    }
    const int wid = tid >> 5, lane = tid & 31;
    if (lane == 0) { wsum[wid] = (double)vs; wsq[wid] = (double)vq; }
    __syncthreads();
    if (tid == 0) {
        double a = 0.0, q = 0.0;
        #pragma unroll
        for (int w = 0; w < TPB / 32; ++w) { a += wsum[w]; q += wsq[w]; }
        g_psum[b]   = a;
        g_psumsq[b] = q;
    }
}

__global__ void __launch_bounds__(TPB)
garch_fixup(const float* __restrict__ r,
            const float* __restrict__ omega_p,
            const float* __restrict__ alpha_p,
            const float* __restrict__ beta_p,
            float* __restrict__ out,
            int n, int nblocks, int write_h)
{
    __shared__ double red[TPB], red2[TPB];
    __shared__ float  sh0;
    const int tid = threadIdx.x;

    // independent of main's results: params (written before the graph ran)
    const float beta = *beta_p;
    const int   lim  = (FIXN < n) ? FIXN : n;
    float bp = 1.0f;                                     // beta^tid
    { float bb = beta; int e = tid;
      while (e) { if (e & 1) bp *= bb; bb *= bb; e >>= 1; } }

#if __CUDA_ARCH__ >= 900
    cudaGridDependencySynchronize();                     // wait for main grid
#endif

    float hhat = 0.0f;
    if (write_h && tid < lim) hhat = out[(long long)n + tid];

    {
        double a0 = 0.0, a1 = 0.0, q0 = 0.0, q1 = 0.0;
        int i = tid;
        for (; i + TPB < nblocks; i += 2 * TPB) {
            a0 += g_psum[i];        q0 += g_psumsq[i];
            a1 += g_psum[i + TPB];  q1 += g_psumsq[i + TPB];
        }
        for (; i < nblocks; i += TPB) { a0 += g_psum[i]; q0 += g_psumsq[i]; }
        red[tid]  = a0 + a1;
        red2[tid] = q0 + q1;
    }
    __syncthreads();
    for (int s = TPB / 2; s; s >>= 1) {
        if (tid < s) { red[tid] += red[tid + s]; red2[tid] += red2[tid + s]; }
        __syncthreads();
    }
    if (tid == 0) {
        double S = red[0], Q = red2[0];
        sh0 = (float)((Q - S * S / (double)n) / (double)(n - 1));
    }
    __syncthreads();

    const float h0 = sh0;
    if (write_h) {
        // h[t] = h_hat[t] + beta^t * h0 (linearity); lim <= TPB: one pass
        if (tid < lim) {
            float hh = (tid == 0) ? h0 : fmaf(bp, h0, hhat);
            out[(long long)n + tid] = hh;
            out[tid] = fsqrt_ap(hh);
        }
    } else {
        if (tid == 0) {                                  // rare fallback
            float omega = *omega_p, alpha = *alpha_p;
            float h = h0;
            out[0] = fsqrt_ap(h);
            for (int t = 1; t < lim; ++t) {
                float rv = r[t - 1];
                h = fmaf(beta, h, fmaf(alpha * rv, rv, omega));
                out[t] = fsqrt_ap(h);
            }
        }
    }
}

extern "C" void kernel_launch(void* const* d_in, const int* in_sizes, int n_in,
                              void* d_out, int out_size)
{
    const float* r  = (const float*)d_in[0];
    const float* om = (const float*)d_in[1];
    const float* al = (const float*)d_in[2];
    const float* be = (const float*)d_in[3];
    float* out = (float*)d_out;

    const int n = in_sizes[0];
    const int write_h = (out_size >= 2 * n) ? 1 : 0;

    int nblocks = (n + OPB - 1) / OPB;
    if (nblocks < 1)    nblocks = 1;
    if (nblocks > MAXB) nblocks = MAXB;

    garch_main<<<nblocks, TPB>>>(r, om, al, be, out, n, write_h);

    // fixup with PDL: its launch overlaps garch_main's execution; the device-
    // side cudaGridDependencySynchronize preserves ordering. Fall back to a
    // normal launch if the attribute is rejected.
    cudaLaunchConfig_t cfg = {};
    cfg.gridDim  = dim3(1, 1, 1);
    cfg.blockDim = dim3(TPB, 1, 1);
    cfg.dynamicSmemBytes = 0;
    cfg.stream = 0;                                       // legacy default stream
    cudaLaunchAttribute attrs[1];
    attrs[0].id = cudaLaunchAttributeProgrammaticStreamSerialization;
    attrs[0].val.programmaticStreamSerializationAllowed = 1;
    cfg.attrs = attrs;
    cfg.numAttrs = 1;

    cudaError_t err = cudaLaunchKernelEx(&cfg, garch_fixup,
                                         r, om, al, be, out, n, nblocks, write_h);
    if (err != cudaSuccess) {
        (void)cudaGetLastError();                         // clear sticky error
        garch_fixup<<<1, TPB>>>(r, om, al, be, out, n, nblocks, write_h);
    }
}

// round 17
// speedup vs baseline: 1.1552x; 1.0360x over previous
#include <cuda_runtime.h>

// GARCH(1,1): h[t] = (omega + alpha*r[t-1]^2) + beta*h[t-1], h[0] = var(r, ddof=1)
// out[0..n) = sqrt(h), out[n..2n) = h
//
// Measured-best fused pipeline (R3/R15: padded-smem staging, f32x2 drivers,
// in-place per-thread 32-chunk recurrence, exact Hillis-Steele stitch, carry
// applied at read, float4 STG, sqrt.approx) with a PROGRESSIVE variance
// reduction replacing the last-block ticket: every block publishes its fp64
// partial + release flag; block 0 (wave-1 resident) streams the partials in
// a FIXED slot order as they arrive, so when the last worker finishes, the
// reduction is already done and only a ~1us patch remains. Deterministic
// (fixed summation order), graph-safe (flags reset inline each run).
// beta<1 => contractive (beta^256 ~ 8e-19 < fp32 ulp): 256-elem warm-up halo
// per tile; intra-block stitch exact. True h[t] = h_hat[t] + beta^t*h0
// (linearity); the h0 term only matters for t < ~100 (patched by block 0).

#define TPB   256
#define CPT   32
#define TILE  (TPB*CPT)        // 8192
#define HALO  256
#define OPB   (TILE - HALO)    // 7936 outputs per block, 4-aligned
#define QOUT  (OPB/4)          // 1984
#define FIXN  256
#define MAXB  4096

__device__ double g_psum[MAXB];
__device__ double g_psumsq[MAXB];
__device__ int    g_flag[MAXB];          // zero-initialized; reset each run

__device__ __forceinline__ int padidx(int k) { return k + (k >> 5); }

__device__ __forceinline__ float fsqrt_ap(float x) {
    float y; asm("sqrt.approx.f32 %0, %1;" : "=f"(y) : "f"(x)); return y;
}
// packed f32x2 (sm_100+)
__device__ __forceinline__ unsigned long long pk2(float lo, float hi) {
    unsigned long long d;
    asm("mov.b64 %0, {%1, %2};" : "=l"(d) : "r"(__float_as_uint(lo)), "r"(__float_as_uint(hi)));
    return d;
}
__device__ __forceinline__ void upk2(unsigned long long v, float& lo, float& hi) {
    unsigned a, b; asm("mov.b64 {%0, %1}, %2;" : "=r"(a), "=r"(b) : "l"(v));
    lo = __uint_as_float(a); hi = __uint_as_float(b);
}
__device__ __forceinline__ unsigned long long mul2(unsigned long long a, unsigned long long b) {
    unsigned long long d; asm("mul.rn.f32x2 %0, %1, %2;" : "=l"(d) : "l"(a), "l"(b)); return d;
}
__device__ __forceinline__ unsigned long long add2(unsigned long long a, unsigned long long b) {
    unsigned long long d; asm("add.rn.f32x2 %0, %1, %2;" : "=l"(d) : "l"(a), "l"(b)); return d;
}
__device__ __forceinline__ unsigned long long fma2(unsigned long long a, unsigned long long b, unsigned long long c) {
    unsigned long long d; asm("fma.rn.f32x2 %0, %1, %2, %3;" : "=l"(d) : "l"(a), "l"(b), "l"(c)); return d;
}

__global__ void __launch_bounds__(TPB)
garch_fused(const float* __restrict__ r,
            const float* __restrict__ omega_p,
            const float* __restrict__ alpha_p,
            const float* __restrict__ beta_p,
            float* __restrict__ out,
            int n, int nblocks, int write_h)
{
    __shared__ __align__(16) float bpad[TILE + TILE/32];
    __shared__ float  sscan[TPB];
    __shared__ float  powtab[CPT];          // beta^(j+1)
    __shared__ double wsum[TPB/32], wsq[TPB/32];
    __shared__ float  sh0;

    const int   tid   = threadIdx.x;
    const int   b     = blockIdx.x;
    const float omega = *omega_p;
    const float alpha = *alpha_p;
    const float beta  = *beta_p;

    // outputs: t in [b*OPB, b*OPB+OPB) ∩ [0,n). tile index k = t - t0.
    const long long t0 = (long long)b * OPB - HALO;   // k=0 <-> t=t0
    const long long A  = t0 - 1;                      // driver r index: g = A + k

    float vs = 0.0f, vq = 0.0f;
    unsigned long long vs2 = 0ull, vq2 = 0ull;

    const bool fast = (b >= 1) && ((long long)(b + 1) * OPB <= (long long)n)
                      && ((n & 3) == 0);

    // ---- Phase 1: drivers b[k] = omega + alpha*r[g]^2, variance partials ----
    if (fast) {
        const float4* __restrict__ r4 = (const float4*)(r + (A - 3)); // 16B aligned
        const unsigned long long alpha2 = pk2(alpha, alpha);
        const unsigned long long omega2 = pk2(omega, omega);
        #pragma unroll
        for (int it = 0; it < 8; ++it) {
            int q = tid + it * TPB;
            float4 v = r4[q];
            int k0 = 4 * q - 3;
            if (it == 0) {                       // edge: k may be <0 / <HALO
                #pragma unroll
                for (int e = 0; e < 4; ++e) {
                    int k = k0 + e;
                    float rv = (e == 0) ? v.x : (e == 1) ? v.y : (e == 2) ? v.z : v.w;
                    if (k >= 0) {
                        float rr = rv * rv;
                        bpad[padidx(k)] = fmaf(alpha, rr, omega);
                        if (k >= HALO) { vs += rv; vq += rr; }
                    }
                }
            } else {                              // packed f32x2 math
                unsigned long long v01 = pk2(v.x, v.y), v23 = pk2(v.z, v.w);
                unsigned long long rr01 = mul2(v01, v01), rr23 = mul2(v23, v23);
                unsigned long long b01 = fma2(alpha2, rr01, omega2);
                unsigned long long b23 = fma2(alpha2, rr23, omega2);
                vs2 = add2(vs2, v01);  vs2 = add2(vs2, v23);
                vq2 = add2(vq2, rr01); vq2 = add2(vq2, rr23);
                float x0, x1, x2, x3;
                upk2(b01, x0, x1); upk2(b23, x2, x3);
                bpad[padidx(k0 + 0)] = x0;
                bpad[padidx(k0 + 1)] = x1;
                bpad[padidx(k0 + 2)] = x2;
                bpad[padidx(k0 + 3)] = x3;
            }
        }
        if (tid < 3) {                            // top 3 elements k=8189..8191
            int k = TILE - 3 + tid;
            float rv = r[A + k];
            float rr = rv * rv;
            bpad[padidx(k)] = fmaf(alpha, rr, omega);
            vs += rv; vq += rr;
        }
    } else {
        #pragma unroll 4
        for (int it = 0; it < TILE / TPB; ++it) {
            int k = tid + it * TPB;
            long long g = A + k;
            float bb = 0.0f;
            if (g >= 0 && g <= (long long)n - 2) {
                float rv = r[g];
                float rr = rv * rv;
                bb = fmaf(alpha, rr, omega);
                if (k >= HALO) { vs += rv; vq += rr; }
            }
            bpad[padidx(k)] = bb;
        }
    }
    if (b == 0 && tid == 0) {                     // r[n-1]: variance only
        float rv = r[n - 1];
        vs += rv; vq = fmaf(rv, rv, vq);
    }
    __syncthreads();

    // ---- Phase 2: per-thread serial recurrence from zero state (in place) ----
    {
        float h = 0.0f;
        const int base = 33 * tid;                // padidx(tid*32)
        #pragma unroll
        for (int j = 0; j < CPT; ++j) {
            h = fmaf(beta, h, bpad[base + j]);
            bpad[base + j] = h;                   // p[j] stays in shared
        }
        sscan[tid] = h;
    }
    if (tid < CPT) {                              // powtab[j] = beta^(j+1)
        float p = 1.0f, bb = beta; int e = tid + 1;
        while (e) { if (e & 1) p *= bb; bb *= bb; e >>= 1; }
        powtab[tid] = p;
    }
    __syncthreads();

    // ---- Phase 3: exact stitch S_i = E_i + beta^32 * S_{i-1} ----
    float b2 = beta * beta, b4 = b2 * b2, b8 = b4 * b4, b16 = b8 * b8;
    float mpow = b16 * b16;                       // beta^32
    #pragma unroll
    for (int d = 1; d < TPB; d <<= 1) {
        float v  = sscan[tid];
        float lo = (tid >= d) ? sscan[tid - d] : 0.0f;
        __syncthreads();
        sscan[tid] = fmaf(mpow, lo, v);
        mpow *= mpow;
        __syncthreads();
    }

    // ---- Phase 4: apply carry at read, vectorized stores ----
    if (fast) {
        #pragma unroll
        for (int it = 0; it < 8; ++it) {
            int q = tid + it * TPB;
            if (q < QOUT) {
                int k  = HALO + 4 * q;
                int c  = k >> 5;                  // >= 8 here
                float cy = sscan[c - 1];
                int pb = padidx(k);               // 4 consecutive, no pad cross
                int pj = k & 31;
                float h0 = fmaf(powtab[pj + 0], cy, bpad[pb + 0]);
                float h1 = fmaf(powtab[pj + 1], cy, bpad[pb + 1]);
                float h2 = fmaf(powtab[pj + 2], cy, bpad[pb + 2]);
                float h3 = fmaf(powtab[pj + 3], cy, bpad[pb + 3]);
                long long t = (long long)b * OPB + 4 * (long long)q;
                float4 sv = make_float4(fsqrt_ap(h0), fsqrt_ap(h1),
                                        fsqrt_ap(h2), fsqrt_ap(h3));
                *(float4*)(out + t) = sv;
                if (write_h) *(float4*)(out + n + t) = make_float4(h0, h1, h2, h3);
            }
        }
    } else {
        #pragma unroll 4
        for (int it = 0; it < TILE / TPB; ++it) {
            int k = tid + it * TPB;
            if (k < HALO) continue;
            long long t = t0 + k;
            if (t < (long long)n) {
                int c = k >> 5;
                float cy = (c > 0) ? sscan[c - 1] : 0.0f;
                float h = fmaf(powtab[k & 31], cy, bpad[padidx(k)]);
                out[t] = fsqrt_ap(h);
                if (write_h) out[(long long)n + t] = h;
            }
        }
    }

    // ---- Phase 5: variance reduce -> publish partial + release flag ----
    {
        float a_, b_;
        upk2(vs2, a_, b_); vs += a_ + b_;
        upk2(vq2, a_, b_); vq += a_ + b_;
    }
    unsigned msk = 0xFFFFFFFFu;
    #pragma unroll
    for (int off = 16; off; off >>= 1) {
        vs += __shfl_down_sync(msk, vs, off);
        vq += __shfl_down_sync(msk, vq, off);
    }
    const int wid = tid >> 5, lane = tid & 31;
    if (lane == 0) { wsum[wid] = (double)vs; wsq[wid] = (double)vq; }
    __syncthreads();
    if (tid == 0) {
        double a = 0.0, q = 0.0;
        #pragma unroll
        for (int w = 0; w < TPB / 32; ++w) { a += wsum[w]; q += wsq[w]; }
        g_psum[b]   = a;
        g_psumsq[b] = q;
        __threadfence();                          // release partial before flag
        *((volatile int*)&g_flag[b]) = 1;
    }
    if (b != 0) return;                           // workers exit clean

    // ================= block 0: progressive collector =================
    // Each thread consumes slots tid, tid+TPB, ... IN ORDER as they arrive
    // (fixed summation order => deterministic). Flags reset for next replay.
    double* red  = (double*)bpad;                 // reuse staging buffer
    double* red2 = red + TPB;
    {
        volatile int* vflag = (volatile int*)g_flag;
        double a = 0.0, q = 0.0;
        for (int i = tid; i < nblocks; i += TPB) {
            int spins = 0;
            while (vflag[i] == 0) {               // wait for slot i
                if (++spins > 32) { __nanosleep(128); spins = 0; }
            }
            __threadfence();                      // acquire: partial visible
            a += g_psum[i];
            q += g_psumsq[i];
            g_flag[i] = 0;                        // reset for next graph replay
        }
        red[tid] = a; red2[tid] = q;
    }
    __syncthreads();
    for (int s = TPB / 2; s; s >>= 1) {
        if (tid < s) { red[tid] += red[tid + s]; red2[tid] += red2[tid + s]; }
        __syncthreads();
    }
    if (tid == 0) {
        double S = red[0], Q = red2[0];
        sh0 = (float)((Q - S * S / (double)n) / (double)(n - 1));
    }
    __syncthreads();

    // patch t < FIXN: h[t] = h_hat[t] + beta^t * h0 (block 0 wrote h_hat itself)
    const float h0v = sh0;
    const int   lim = (FIXN < n) ? FIXN : n;
    if (write_h) {
        if (tid < lim) {                          // lim <= TPB: one pass
            float bp = 1.0f, bb = beta; int e = tid;
            while (e) { if (e & 1) bp *= bb; bb *= bb; e >>= 1; }
            float hh = (tid == 0) ? h0v : fmaf(bp, h0v, out[(long long)n + tid]);
            out[(long long)n + tid] = hh;
            out[tid] = fsqrt_ap(hh);
        }
    } else {
        if (tid == 0) {                           // rare fallback: serial prefix
            float h = h0v;
            out[0] = fsqrt_ap(h);
            for (int t = 1; t < lim; ++t) {
                float rv = r[t - 1];
                h = fmaf(beta, h, fmaf(alpha * rv, rv, omega));
                out[t] = fsqrt_ap(h);
            }
        }
    }
}

extern "C" void kernel_launch(void* const* d_in, const int* in_sizes, int n_in,
                              void* d_out, int out_size)
{
    const float* r  = (const float*)d_in[0];
    const float* om = (const float*)d_in[1];
    const float* al = (const float*)d_in[2];
    const float* be = (const float*)d_in[3];
    float* out = (float*)d_out;

    const int n = in_sizes[0];
    const int write_h = (out_size >= 2 * n) ? 1 : 0;

    int nblocks = (n + OPB - 1) / OPB;
    if (nblocks < 1)    nblocks = 1;
    if (nblocks > MAXB) nblocks = MAXB;

    garch_fused<<<nblocks, TPB>>>(r, om, al, be, out, n, nblocks, write_h);
}